// round 13
// baseline (speedup 1.0000x reference)
#include <cuda_runtime.h>
#include <cstdint>

// ---------------- problem constants ----------------
#define BATCH   32
#define HW      56
#define CDIM    512
#define WSZ     7
#define NWIN    2048
#define TTOK    49
#define MTOT    (NWIN * TTOK)   // 100352
#define NQKV    1536

// GEMM tiling: 64x128 CTA tile, 8 warps of 32x32, 3 CTAs/SM
#define BM 64
#define BN 128
#define BK 16
#define STAGES 4
#define SPAD 20

// attention smem row pad
#define AP 68

// ---------------- scratch (device globals; no allocs allowed) -------------
__device__ float g_qkv[3ULL * MTOT * CDIM];
__device__ float g_att[(size_t)MTOT * CDIM];            // pre-rounded tf32
__device__ float g_xr[(size_t)BATCH * HW * HW * CDIM];  // rounded x
__device__ float g_wqt[(size_t)NQKV * CDIM];            // rounded w_qkv^T [n][k]
__device__ float g_wpt[(size_t)CDIM * CDIM];            // rounded w_proj^T [n][k]

// map windowed row m -> source/dest row in [B*3136)
__device__ __forceinline__ int win_row_map(int m) {
    int w = m / TTOK, t = m - w * TTOK;
    int b = w >> 6;
    int wi = (w >> 3) & 7;
    int wj = w & 7;
    int r = t / WSZ, c = t - r * WSZ;
    return (b * HW + wi * WSZ + r) * HW + wj * WSZ + c;
}

__device__ __forceinline__ uint32_t f2tf32(float f) {
    uint32_t u;
    asm("cvt.rna.tf32.f32 %0, %1;" : "=r"(u) : "f"(f));
    return u;
}

__device__ __forceinline__ void cp_async16(void* smem_dst, const void* gmem_src) {
    uint32_t s = (uint32_t)__cvta_generic_to_shared(smem_dst);
    asm volatile("cp.async.cg.shared.global [%0], [%1], 16;" :: "r"(s), "l"(gmem_src));
}
__device__ __forceinline__ void cp_commit() {
    asm volatile("cp.async.commit_group;");
}
__device__ __forceinline__ void cp_wait2() {
    asm volatile("cp.async.wait_group 2;");
}

__device__ __forceinline__ void ldsm4(uint32_t& r0, uint32_t& r1, uint32_t& r2,
                                      uint32_t& r3, uint32_t addr) {
    asm volatile("ldmatrix.sync.aligned.m8n8.x4.shared.b16 {%0,%1,%2,%3}, [%4];"
                 : "=r"(r0), "=r"(r1), "=r"(r2), "=r"(r3) : "r"(addr));
}

// ---------------- prep kernels ----------------
__global__ void round_copy(const float* __restrict__ src, float* __restrict__ dst) {
    const size_t i = ((size_t)blockIdx.x * blockDim.x + threadIdx.x) * 4;
    float4 v = *(const float4*)(src + i);
    uint4 r;
    r.x = f2tf32(v.x); r.y = f2tf32(v.y); r.z = f2tf32(v.z); r.w = f2tf32(v.w);
    *(uint4*)(dst + i) = r;
}

// src[R][C] -> dst[C][R], rounded to tf32
__global__ void round_transpose(const float* __restrict__ src, float* __restrict__ dst,
                                int R, int C) {
    __shared__ float t[32][33];
    const int bx = blockIdx.x * 32;
    const int by = blockIdx.y * 32;
    const int tx = threadIdx.x;
    for (int i = threadIdx.y; i < 32; i += 8)
        t[i][tx] = src[(size_t)(by + i) * C + bx + tx];
    __syncthreads();
    for (int i = threadIdx.y; i < 32; i += 8)
        dst[(size_t)(bx + i) * R + by + tx] = __uint_as_float(f2tf32(t[tx][i]));
}

// ---------------- tf32 mma GEMM: 64x128 tile, 32x32 warp tiles ------------
// MODE 0: A = g_xr gathered via win_row_map, W = g_wqt, out -> g_qkv
// MODE 1: A = g_att linear, W = g_wpt, out scattered via win_row_map
template<int NDIM, int MODE>
__global__ __launch_bounds__(256, 3) void mma_gemm(
    const float* __restrict__ bias,
    float* __restrict__ out)
{
    __shared__ __align__(16) float As[STAGES][BM][SPAD];
    __shared__ __align__(16) float Bs[STAGES][BN][SPAD];

    const int tid = threadIdx.x;
    const int lane = tid & 31;
    const int wid  = tid >> 5;
    const int warp_m = wid >> 2;   // 0..1  (32 rows each)
    const int warp_n = wid & 3;    // 0..3  (32 cols each)
    const int bn = blockIdx.x * BN;
    const int bm = blockIdx.y * BM;

    const float* Abase = (MODE == 1) ? (const float*)g_att : (const float*)g_xr;
    const float* Wt    = (MODE == 1) ? (const float*)g_wpt : (const float*)g_wqt;

    // A loader: row = tid>>2 (0..63), quad = (tid&3)*4   (1 cp.async16/thread)
    const int a_srow = tid >> 2;
    const int a_scq  = (tid & 3) * 4;
    const int agrow = (MODE == 0) ? win_row_map(bm + a_srow) : (bm + a_srow);
    const float* aptr = Abase + (size_t)agrow * CDIM + a_scq;

    // B loader: row = tid>>1 (0..127), half = (tid&1)*8  (2 cp.async16/thread)
    const int b_srow = tid >> 1;
    const int b_scq  = (tid & 1) * 8;
    const float* bptr = Wt + (size_t)(bn + b_srow) * CDIM + b_scq;

    float acc[2][4][4] = {};

    const int NIT = CDIM / BK;   // 32

    const int a_row_l = warp_m * 32 + ((lane >> 3) & 1) * 8 + (lane & 7);
    const int a_k_l   = (lane >> 4) * 4;
    const int b_row_l = warp_n * 32 + ((lane >> 4) & 1) * 8 + (lane & 7);
    const int b_k_l   = ((lane >> 3) & 1) * 4;

    const uint32_t sA0 = (uint32_t)__cvta_generic_to_shared(&As[0][0][0]);
    const uint32_t sB0 = (uint32_t)__cvta_generic_to_shared(&Bs[0][0][0]);
    const uint32_t stageA = BM * SPAD * 4;
    const uint32_t stageB = BN * SPAD * 4;

#pragma unroll
    for (int p = 0; p < STAGES - 1; p++) {
        cp_async16(&As[p][a_srow][a_scq], aptr + p * BK);
        const float* bp = bptr + p * BK;
        cp_async16(&Bs[p][b_srow][b_scq],     bp);
        cp_async16(&Bs[p][b_srow][b_scq + 4], bp + 4);
        cp_commit();
    }
    cp_wait2();
    __syncthreads();

    int s = 0;

#pragma unroll 1
    for (int it = 0; it < NIT; ++it) {
#pragma unroll
        for (int ks = 0; ks < 2; ks++) {
            const int k = ks * 8;
            uint32_t af[2][4];
#pragma unroll
            for (int mt = 0; mt < 2; mt++) {
                const uint32_t addr = sA0 + s * stageA +
                    ((uint32_t)(a_row_l + mt * 16) * SPAD + k + a_k_l) * 4;
                ldsm4(af[mt][0], af[mt][1], af[mt][2], af[mt][3], addr);
            }
            uint32_t bf[4][2];
#pragma unroll
            for (int np = 0; np < 2; np++) {
                const uint32_t addr = sB0 + s * stageB +
                    ((uint32_t)(b_row_l + np * 16) * SPAD + k + b_k_l) * 4;
                ldsm4(bf[np * 2][0], bf[np * 2][1], bf[np * 2 + 1][0], bf[np * 2 + 1][1], addr);
            }
#pragma unroll
            for (int mt = 0; mt < 2; mt++)
#pragma unroll
                for (int nt = 0; nt < 4; nt++)
                    asm volatile(
                        "mma.sync.aligned.m16n8k8.row.col.f32.tf32.tf32.f32 "
                        "{%0,%1,%2,%3},{%4,%5,%6,%7},{%8,%9},{%0,%1,%2,%3};"
                        : "+f"(acc[mt][nt][0]), "+f"(acc[mt][nt][1]),
                          "+f"(acc[mt][nt][2]), "+f"(acc[mt][nt][3])
                        : "r"(af[mt][0]), "r"(af[mt][1]), "r"(af[mt][2]), "r"(af[mt][3]),
                          "r"(bf[nt][0]), "r"(bf[nt][1]));
        }

        if (it + STAGES - 1 < NIT) {
            const int ls = (s + STAGES - 1 >= STAGES) ? (s - 1) : (s + STAGES - 1);
            cp_async16(&As[ls][a_srow][a_scq], aptr + (it + STAGES - 1) * BK);
            const float* bp = bptr + (it + STAGES - 1) * BK;
            cp_async16(&Bs[ls][b_srow][b_scq],     bp);
            cp_async16(&Bs[ls][b_srow][b_scq + 4], bp + 4);
        }
        cp_commit();
        cp_wait2();
        __syncthreads();

        s = (s + 1 >= STAGES) ? 0 : (s + 1);
    }

    // ---------------- epilogue ----------------
#pragma unroll
    for (int mt = 0; mt < 2; mt++) {
        const int row0 = bm + warp_m * 32 + mt * 16 + (lane >> 2);
#pragma unroll
        for (int half = 0; half < 2; half++) {
            const int m = row0 + half * 8;
            int dst = 0;
            if (MODE == 1) dst = win_row_map(m);
#pragma unroll
            for (int nt = 0; nt < 4; nt++) {
                const int col0 = bn + warp_n * 32 + nt * 8 + 2 * (lane & 3);
#pragma unroll
                for (int j = 0; j < 2; j++) {
                    const int n = col0 + j;
                    const float v = acc[mt][nt][half * 2 + j] + bias[n];
                    if (MODE == 0) {
                        const int p  = n >> 9;
                        const int cc = n & 511;
                        g_qkv[(size_t)p * MTOT * CDIM + (size_t)m * CDIM + cc] = v;
                    } else {
                        out[(size_t)dst * CDIM + n] = v;
                    }
                }
            }
        }
    }
}

// ---------------- attention: conflict-free float4 version ------------------
__global__ void attn_kernel() {
    __shared__ __align__(16) float qs[4][8 * AP];
    __shared__ __align__(16) float ks[4][8 * AP];
    __shared__ __align__(16) float vs[4][8 * AP];
    __shared__ float ps[4][64];

    const int tid = threadIdx.x;
    const int u   = tid >> 6;
    const int lt  = tid & 63;
    const int unit = blockIdx.x * 4 + u;

    const size_t rowoff = (size_t)unit * CDIM;
    const float* qrow = g_qkv + rowoff;
    const float* krow = g_qkv + (size_t)MTOT * CDIM + rowoff;
    const float* vrow = g_qkv + 2ULL * MTOT * CDIM + rowoff;

#pragma unroll
    for (int j = 0; j < 2; j++) {
        const int f  = lt + 64 * j;
        const int c  = f >> 4;
        const int dd = (f & 15) * 4;
        const int so = c * AP + dd;
        *(float4*)&qs[u][so] = *(const float4*)(qrow + f * 4);
        *(float4*)&ks[u][so] = *(const float4*)(krow + f * 4);
        *(float4*)&vs[u][so] = *(const float4*)(vrow + f * 4);
    }
    __syncthreads();

    const int h = lt >> 3, g = lt & 7;

    float s = 0.f;
    {
        const float* qb = &qs[u][h * AP];
        const float* kb = &ks[u][g * AP];
#pragma unroll
        for (int kk = 0; kk < 16; kk++) {
            float4 qa = *(const float4*)(qb + kk * 4);
            float4 ka = *(const float4*)(kb + kk * 4);
            s = fmaf(qa.x, ka.x, s);
            s = fmaf(qa.y, ka.y, s);
            s = fmaf(qa.z, ka.z, s);
            s = fmaf(qa.w, ka.w, s);
        }
    }
    s *= 0.125f;

    float mx = s;
#pragma unroll
    for (int off = 4; off >= 1; off >>= 1)
        mx = fmaxf(mx, __shfl_xor_sync(0xffffffffu, mx, off));
    float e = __expf(s - mx);
    float sum = e;
#pragma unroll
    for (int off = 4; off >= 1; off >>= 1)
        sum += __shfl_xor_sync(0xffffffffu, sum, off);
    ps[u][lt] = e / sum;
    __syncthreads();

    const int dc = (g + h) & 7;
    const int d0 = dc * 8;
    float p[8];
#pragma unroll
    for (int gg = 0; gg < 8; gg++) p[gg] = ps[u][h * 8 + gg];

    float4 o0 = {0.f, 0.f, 0.f, 0.f};
    float4 o1 = {0.f, 0.f, 0.f, 0.f};
#pragma unroll
    for (int gg = 0; gg < 8; gg++) {
        const float* vb = &vs[u][gg * AP + d0];
        float4 v0 = *(const float4*)(vb);
        float4 v1 = *(const float4*)(vb + 4);
        o0.x = fmaf(p[gg], v0.x, o0.x);
        o0.y = fmaf(p[gg], v0.y, o0.y);
        o0.z = fmaf(p[gg], v0.z, o0.z);
        o0.w = fmaf(p[gg], v0.w, o0.w);
        o1.x = fmaf(p[gg], v1.x, o1.x);
        o1.y = fmaf(p[gg], v1.y, o1.y);
        o1.z = fmaf(p[gg], v1.z, o1.z);
        o1.w = fmaf(p[gg], v1.w, o1.w);
    }

    const int w = unit / TTOK, t = unit - w * TTOK;
    float* obase = g_att + (size_t)w * (TTOK * CDIM) + (size_t)h * (TTOK * 64) + (size_t)t * 64;
    uint4 r0, r1;
    r0.x = f2tf32(o0.x); r0.y = f2tf32(o0.y); r0.z = f2tf32(o0.z); r0.w = f2tf32(o0.w);
    r1.x = f2tf32(o1.x); r1.y = f2tf32(o1.y); r1.z = f2tf32(o1.z); r1.w = f2tf32(o1.w);
    *(uint4*)(obase + d0)     = r0;
    *(uint4*)(obase + d0 + 4) = r1;
}

// ---------------- launch ----------------
extern "C" void kernel_launch(void* const* d_in, const int* in_sizes, int n_in,
                              void* d_out, int out_size) {
    const float* x      = (const float*)d_in[0];
    const float* w_qkv  = (const float*)d_in[1];
    const float* b_qkv  = (const float*)d_in[2];
    const float* w_proj = (const float*)d_in[3];
    const float* b_proj = (const float*)d_in[4];
    float* out = (float*)d_out;

    // prep: rounded x, rounded+transposed weights
    {
        float* xr;  cudaGetSymbolAddress((void**)&xr,  g_xr);
        float* wqt; cudaGetSymbolAddress((void**)&wqt, g_wqt);
        float* wpt; cudaGetSymbolAddress((void**)&wpt, g_wpt);
        const size_t nx = (size_t)BATCH * HW * HW * CDIM;
        round_copy<<<(unsigned)(nx / 4 / 256), 256>>>(x, xr);
        {
            dim3 grid(NQKV / 32, CDIM / 32);
            round_transpose<<<grid, dim3(32, 8)>>>(w_qkv, wqt, CDIM, NQKV);
        }
        {
            dim3 grid(CDIM / 32, CDIM / 32);
            round_transpose<<<grid, dim3(32, 8)>>>(w_proj, wpt, CDIM, CDIM);
        }
    }
    {
        dim3 grid(NQKV / BN, MTOT / BM);   // 12 x 1568
        mma_gemm<NQKV, 0><<<grid, 256>>>(b_qkv, nullptr);
    }
    {
        attn_kernel<<<MTOT / 4, 256>>>();
    }
    {
        dim3 grid(CDIM / BN, MTOT / BM);   // 4 x 1568
        mma_gemm<CDIM, 1><<<grid, 256>>>(b_proj, out);
    }
}

// round 14
// speedup vs baseline: 1.1461x; 1.1461x over previous
#include <cuda_runtime.h>
#include <cstdint>

// ---------------- problem constants ----------------
#define BATCH   32
#define HW      56
#define CDIM    512
#define WSZ     7
#define NWIN    2048
#define TTOK    49
#define MTOT    (NWIN * TTOK)   // 100352
#define NQKV    1536

// proj GEMM tiling (round-12 proven config)
#define BM 128
#define BN 128
#define BK 16
#define STAGES 4
#define SPAD 20

// qkv GEMM tiling: 128x256 tile, 8 warps of 64x64
#define QBM 128
#define QBN 256

// attention smem row pad
#define AP 68

// ---------------- scratch (device globals; no allocs allowed) -------------
__device__ float g_qkv[3ULL * MTOT * CDIM];
__device__ float g_att[(size_t)MTOT * CDIM];            // pre-rounded tf32
__device__ float g_xr[(size_t)BATCH * HW * HW * CDIM];  // rounded x
__device__ float g_wqt[(size_t)NQKV * CDIM];            // rounded w_qkv^T [n][k]
__device__ float g_wpt[(size_t)CDIM * CDIM];            // rounded w_proj^T [n][k]

// map windowed row m -> source/dest row in [B*3136)
__device__ __forceinline__ int win_row_map(int m) {
    int w = m / TTOK, t = m - w * TTOK;
    int b = w >> 6;
    int wi = (w >> 3) & 7;
    int wj = w & 7;
    int r = t / WSZ, c = t - r * WSZ;
    return (b * HW + wi * WSZ + r) * HW + wj * WSZ + c;
}

__device__ __forceinline__ uint32_t f2tf32(float f) {
    uint32_t u;
    asm("cvt.rna.tf32.f32 %0, %1;" : "=r"(u) : "f"(f));
    return u;
}

__device__ __forceinline__ void cp_async16(void* smem_dst, const void* gmem_src) {
    uint32_t s = (uint32_t)__cvta_generic_to_shared(smem_dst);
    asm volatile("cp.async.cg.shared.global [%0], [%1], 16;" :: "r"(s), "l"(gmem_src));
}
__device__ __forceinline__ void cp_commit() {
    asm volatile("cp.async.commit_group;");
}
__device__ __forceinline__ void cp_wait2() {
    asm volatile("cp.async.wait_group 2;");
}

__device__ __forceinline__ void ldsm4(uint32_t& r0, uint32_t& r1, uint32_t& r2,
                                      uint32_t& r3, uint32_t addr) {
    asm volatile("ldmatrix.sync.aligned.m8n8.x4.shared.b16 {%0,%1,%2,%3}, [%4];"
                 : "=r"(r0), "=r"(r1), "=r"(r2), "=r"(r3) : "r"(addr));
}

#define MMA_TF32(acc4, a0, a1, a2, a3, b0, b1) \
    asm volatile( \
        "mma.sync.aligned.m16n8k8.row.col.f32.tf32.tf32.f32 " \
        "{%0,%1,%2,%3},{%4,%5,%6,%7},{%8,%9},{%0,%1,%2,%3};" \
        : "+f"((acc4)[0]), "+f"((acc4)[1]), "+f"((acc4)[2]), "+f"((acc4)[3]) \
        : "r"(a0), "r"(a1), "r"(a2), "r"(a3), "r"(b0), "r"(b1))

// ---------------- prep kernels ----------------
__global__ void round_copy(const float* __restrict__ src, float* __restrict__ dst) {
    const size_t i = ((size_t)blockIdx.x * blockDim.x + threadIdx.x) * 4;
    float4 v = *(const float4*)(src + i);
    uint4 r;
    r.x = f2tf32(v.x); r.y = f2tf32(v.y); r.z = f2tf32(v.z); r.w = f2tf32(v.w);
    *(uint4*)(dst + i) = r;
}

// src[R][C] -> dst[C][R], rounded to tf32
__global__ void round_transpose(const float* __restrict__ src, float* __restrict__ dst,
                                int R, int C) {
    __shared__ float t[32][33];
    const int bx = blockIdx.x * 32;
    const int by = blockIdx.y * 32;
    const int tx = threadIdx.x;
    for (int i = threadIdx.y; i < 32; i += 8)
        t[i][tx] = src[(size_t)(by + i) * C + bx + tx];
    __syncthreads();
    for (int i = threadIdx.y; i < 32; i += 8)
        dst[(size_t)(bx + i) * R + by + tx] = __uint_as_float(f2tf32(t[tx][i]));
}

// ---------------- qkv GEMM: 128x256 tile, 64x64 warp tiles, 1 CTA/SM ------
__global__ __launch_bounds__(256, 1) void qkv_gemm(const float* __restrict__ bias) {
    __shared__ __align__(16) float As[STAGES][QBM][SPAD];
    __shared__ __align__(16) float Bs[STAGES][QBN][SPAD];

    const int tid = threadIdx.x;
    const int lane = tid & 31;
    const int wid  = tid >> 5;
    const int warp_m = wid >> 2;   // 0..1  (64 rows)
    const int warp_n = wid & 3;    // 0..3  (64 cols)
    const int bn = blockIdx.x * QBN;
    const int bm = blockIdx.y * QBM;

    // A loader: row = tid>>1 (0..127), half = (tid&1)*8  (2 cp16/thread)
    const int a_srow = tid >> 1;
    const int a_scq  = (tid & 1) * 8;
    const float* aptr = g_xr + (size_t)win_row_map(bm + a_srow) * CDIM + a_scq;
    // B loader: row = tid (0..255), 4 cp16/thread
    const float* bptr = g_wqt + (size_t)(bn + tid) * CDIM;

    float acc[4][8][4] = {};

    const int NIT = CDIM / BK;   // 32

    const int a_row_l = warp_m * 64 + ((lane >> 3) & 1) * 8 + (lane & 7);
    const int a_k_l   = (lane >> 4) * 4;
    const int b_row_l = warp_n * 64 + ((lane >> 4) & 1) * 8 + (lane & 7);
    const int b_k_l   = ((lane >> 3) & 1) * 4;

    const uint32_t sA0 = (uint32_t)__cvta_generic_to_shared(&As[0][0][0]);
    const uint32_t sB0 = (uint32_t)__cvta_generic_to_shared(&Bs[0][0][0]);
    const uint32_t stageA = QBM * SPAD * 4;
    const uint32_t stageB = QBN * SPAD * 4;

#pragma unroll
    for (int p = 0; p < STAGES - 1; p++) {
        const float* ap = aptr + p * BK;
        cp_async16(&As[p][a_srow][a_scq],     ap);
        cp_async16(&As[p][a_srow][a_scq + 4], ap + 4);
        const float* bp = bptr + p * BK;
#pragma unroll
        for (int q = 0; q < 4; q++)
            cp_async16(&Bs[p][tid][q * 4], bp + q * 4);
        cp_commit();
    }
    cp_wait2();
    __syncthreads();

    int s = 0;

#pragma unroll 1
    for (int it = 0; it < NIT; ++it) {
#pragma unroll
        for (int ks = 0; ks < 2; ks++) {
            const int k = ks * 8;
            uint32_t af[4][4];
#pragma unroll
            for (int mt = 0; mt < 4; mt++) {
                const uint32_t addr = sA0 + s * stageA +
                    ((uint32_t)(a_row_l + mt * 16) * SPAD + k + a_k_l) * 4;
                ldsm4(af[mt][0], af[mt][1], af[mt][2], af[mt][3], addr);
            }
            uint32_t bf[8][2];
#pragma unroll
            for (int np = 0; np < 4; np++) {
                const uint32_t addr = sB0 + s * stageB +
                    ((uint32_t)(b_row_l + np * 16) * SPAD + k + b_k_l) * 4;
                ldsm4(bf[np * 2][0], bf[np * 2][1], bf[np * 2 + 1][0], bf[np * 2 + 1][1], addr);
            }
#pragma unroll
            for (int mt = 0; mt < 4; mt++)
#pragma unroll
                for (int nt = 0; nt < 8; nt++)
                    MMA_TF32(acc[mt][nt], af[mt][0], af[mt][1], af[mt][2], af[mt][3],
                             bf[nt][0], bf[nt][1]);
        }

        if (it + STAGES - 1 < NIT) {
            const int ls = (s + STAGES - 1 >= STAGES) ? (s - 1) : (s + STAGES - 1);
            const float* ap = aptr + (it + STAGES - 1) * BK;
            cp_async16(&As[ls][a_srow][a_scq],     ap);
            cp_async16(&As[ls][a_srow][a_scq + 4], ap + 4);
            const float* bp = bptr + (it + STAGES - 1) * BK;
#pragma unroll
            for (int q = 0; q < 4; q++)
                cp_async16(&Bs[ls][tid][q * 4], bp + q * 4);
        }
        cp_commit();
        cp_wait2();
        __syncthreads();

        s = (s + 1 >= STAGES) ? 0 : (s + 1);
    }

    // epilogue: scatter into q/k/v parts of g_qkv
#pragma unroll
    for (int mt = 0; mt < 4; mt++) {
        const int row0 = bm + warp_m * 64 + mt * 16 + (lane >> 2);
#pragma unroll
        for (int half = 0; half < 2; half++) {
            const int m = row0 + half * 8;
#pragma unroll
            for (int nt = 0; nt < 8; nt++) {
                const int col0 = bn + warp_n * 64 + nt * 8 + 2 * (lane & 3);
#pragma unroll
                for (int j = 0; j < 2; j++) {
                    const int n = col0 + j;
                    const float v = acc[mt][nt][half * 2 + j] + bias[n];
                    const int p  = n >> 9;
                    const int cc = n & 511;
                    g_qkv[(size_t)p * MTOT * CDIM + (size_t)m * CDIM + cc] = v;
                }
            }
        }
    }
}

// ---------------- proj GEMM (round-12 config, MODE 1) ----------------------
__global__ __launch_bounds__(256, 2) void proj_gemm(const float* __restrict__ bias,
                                                    float* __restrict__ out) {
    __shared__ __align__(16) float As[STAGES][BM][SPAD];
    __shared__ __align__(16) float Bs[STAGES][BM][SPAD];

    const int tid = threadIdx.x;
    const int lane = tid & 31;
    const int wid  = tid >> 5;
    const int warp_m = wid >> 2;
    const int warp_n = wid & 3;
    const int bn = blockIdx.x * BN;
    const int bm = blockIdx.y * BM;

    const int srow = tid >> 1;
    const int scq  = (tid & 1) * 8;
    const float* aptr = g_att + (size_t)(bm + srow) * CDIM + scq;
    const float* bptr = g_wpt + (size_t)(bn + srow) * CDIM + scq;

    float acc[4][4][4] = {};

    const int NIT = CDIM / BK;

    const int a_row_l = warp_m * 64 + ((lane >> 3) & 1) * 8 + (lane & 7);
    const int a_k_l   = (lane >> 4) * 4;
    const int b_row_l = warp_n * 32 + ((lane >> 4) & 1) * 8 + (lane & 7);
    const int b_k_l   = ((lane >> 3) & 1) * 4;

    const uint32_t sA0 = (uint32_t)__cvta_generic_to_shared(&As[0][0][0]);
    const uint32_t sB0 = (uint32_t)__cvta_generic_to_shared(&Bs[0][0][0]);
    const uint32_t stageB = BM * SPAD * 4;

#pragma unroll
    for (int p = 0; p < STAGES - 1; p++) {
        const float* ap = aptr + p * BK;
        cp_async16(&As[p][srow][scq],     ap);
        cp_async16(&As[p][srow][scq + 4], ap + 4);
        const float* bp = bptr + p * BK;
        cp_async16(&Bs[p][srow][scq],     bp);
        cp_async16(&Bs[p][srow][scq + 4], bp + 4);
        cp_commit();
    }
    cp_wait2();
    __syncthreads();

    int s = 0;

#pragma unroll 1
    for (int it = 0; it < NIT; ++it) {
#pragma unroll
        for (int ks = 0; ks < 2; ks++) {
            const int k = ks * 8;
            uint32_t af[4][4];
#pragma unroll
            for (int mt = 0; mt < 4; mt++) {
                const uint32_t addr = sA0 + s * stageB +
                    ((uint32_t)(a_row_l + mt * 16) * SPAD + k + a_k_l) * 4;
                ldsm4(af[mt][0], af[mt][1], af[mt][2], af[mt][3], addr);
            }
            uint32_t bf[4][2];
#pragma unroll
            for (int np = 0; np < 2; np++) {
                const uint32_t addr = sB0 + s * stageB +
                    ((uint32_t)(b_row_l + np * 16) * SPAD + k + b_k_l) * 4;
                ldsm4(bf[np * 2][0], bf[np * 2][1], bf[np * 2 + 1][0], bf[np * 2 + 1][1], addr);
            }
#pragma unroll
            for (int mt = 0; mt < 4; mt++)
#pragma unroll
                for (int nt = 0; nt < 4; nt++)
                    MMA_TF32(acc[mt][nt], af[mt][0], af[mt][1], af[mt][2], af[mt][3],
                             bf[nt][0], bf[nt][1]);
        }

        if (it + STAGES - 1 < NIT) {
            const int ls = (s + STAGES - 1 >= STAGES) ? (s - 1) : (s + STAGES - 1);
            const float* ap = aptr + (it + STAGES - 1) * BK;
            cp_async16(&As[ls][srow][scq],     ap);
            cp_async16(&As[ls][srow][scq + 4], ap + 4);
            const float* bp = bptr + (it + STAGES - 1) * BK;
            cp_async16(&Bs[ls][srow][scq],     bp);
            cp_async16(&Bs[ls][srow][scq + 4], bp + 4);
        }
        cp_commit();
        cp_wait2();
        __syncthreads();

        s = (s + 1 >= STAGES) ? 0 : (s + 1);
    }

#pragma unroll
    for (int mt = 0; mt < 4; mt++) {
        const int row0 = bm + warp_m * 64 + mt * 16 + (lane >> 2);
#pragma unroll
        for (int half = 0; half < 2; half++) {
            const int m = row0 + half * 8;
            const int dst = win_row_map(m);
#pragma unroll
            for (int nt = 0; nt < 4; nt++) {
                const int col0 = bn + warp_n * 32 + nt * 8 + 2 * (lane & 3);
#pragma unroll
                for (int j = 0; j < 2; j++) {
                    const int n = col0 + j;
                    out[(size_t)dst * CDIM + n] = acc[mt][nt][half * 2 + j] + bias[n];
                }
            }
        }
    }
}

// ---------------- attention (round-12 conflict-free float4) ----------------
__global__ void attn_kernel() {
    __shared__ __align__(16) float qs[4][8 * AP];
    __shared__ __align__(16) float ks[4][8 * AP];
    __shared__ __align__(16) float vs[4][8 * AP];
    __shared__ float ps[4][64];

    const int tid = threadIdx.x;
    const int u   = tid >> 6;
    const int lt  = tid & 63;
    const int unit = blockIdx.x * 4 + u;

    const size_t rowoff = (size_t)unit * CDIM;
    const float* qrow = g_qkv + rowoff;
    const float* krow = g_qkv + (size_t)MTOT * CDIM + rowoff;
    const float* vrow = g_qkv + 2ULL * MTOT * CDIM + rowoff;

#pragma unroll
    for (int j = 0; j < 2; j++) {
        const int f  = lt + 64 * j;
        const int c  = f >> 4;
        const int dd = (f & 15) * 4;
        const int so = c * AP + dd;
        *(float4*)&qs[u][so] = *(const float4*)(qrow + f * 4);
        *(float4*)&ks[u][so] = *(const float4*)(krow + f * 4);
        *(float4*)&vs[u][so] = *(const float4*)(vrow + f * 4);
    }
    __syncthreads();

    const int h = lt >> 3, g = lt & 7;

    float s = 0.f;
    {
        const float* qb = &qs[u][h * AP];
        const float* kb = &ks[u][g * AP];
#pragma unroll
        for (int kk = 0; kk < 16; kk++) {
            float4 qa = *(const float4*)(qb + kk * 4);
            float4 ka = *(const float4*)(kb + kk * 4);
            s = fmaf(qa.x, ka.x, s);
            s = fmaf(qa.y, ka.y, s);
            s = fmaf(qa.z, ka.z, s);
            s = fmaf(qa.w, ka.w, s);
        }
    }
    s *= 0.125f;

    float mx = s;
#pragma unroll
    for (int off = 4; off >= 1; off >>= 1)
        mx = fmaxf(mx, __shfl_xor_sync(0xffffffffu, mx, off));
    float e = __expf(s - mx);
    float sum = e;
#pragma unroll
    for (int off = 4; off >= 1; off >>= 1)
        sum += __shfl_xor_sync(0xffffffffu, sum, off);
    ps[u][lt] = e / sum;
    __syncthreads();

    const int dc = (g + h) & 7;
    const int d0 = dc * 8;
    float p[8];
#pragma unroll
    for (int gg = 0; gg < 8; gg++) p[gg] = ps[u][h * 8 + gg];

    float4 o0 = {0.f, 0.f, 0.f, 0.f};
    float4 o1 = {0.f, 0.f, 0.f, 0.f};
#pragma unroll
    for (int gg = 0; gg < 8; gg++) {
        const float* vb = &vs[u][gg * AP + d0];
        float4 v0 = *(const float4*)(vb);
        float4 v1 = *(const float4*)(vb + 4);
        o0.x = fmaf(p[gg], v0.x, o0.x);
        o0.y = fmaf(p[gg], v0.y, o0.y);
        o0.z = fmaf(p[gg], v0.z, o0.z);
        o0.w = fmaf(p[gg], v0.w, o0.w);
        o1.x = fmaf(p[gg], v1.x, o1.x);
        o1.y = fmaf(p[gg], v1.y, o1.y);
        o1.z = fmaf(p[gg], v1.z, o1.z);
        o1.w = fmaf(p[gg], v1.w, o1.w);
    }

    const int w = unit / TTOK, t = unit - w * TTOK;
    float* obase = g_att + (size_t)w * (TTOK * CDIM) + (size_t)h * (TTOK * 64) + (size_t)t * 64;
    uint4 r0, r1;
    r0.x = f2tf32(o0.x); r0.y = f2tf32(o0.y); r0.z = f2tf32(o0.z); r0.w = f2tf32(o0.w);
    r1.x = f2tf32(o1.x); r1.y = f2tf32(o1.y); r1.z = f2tf32(o1.z); r1.w = f2tf32(o1.w);
    *(uint4*)(obase + d0)     = r0;
    *(uint4*)(obase + d0 + 4) = r1;
}

// ---------------- launch ----------------
extern "C" void kernel_launch(void* const* d_in, const int* in_sizes, int n_in,
                              void* d_out, int out_size) {
    const float* x      = (const float*)d_in[0];
    const float* w_qkv  = (const float*)d_in[1];
    const float* b_qkv  = (const float*)d_in[2];
    const float* w_proj = (const float*)d_in[3];
    const float* b_proj = (const float*)d_in[4];
    float* out = (float*)d_out;

    // prep: rounded x, rounded+transposed weights
    {
        float* xr;  cudaGetSymbolAddress((void**)&xr,  g_xr);
        float* wqt; cudaGetSymbolAddress((void**)&wqt, g_wqt);
        float* wpt; cudaGetSymbolAddress((void**)&wpt, g_wpt);
        const size_t nx = (size_t)BATCH * HW * HW * CDIM;
        round_copy<<<(unsigned)(nx / 4 / 256), 256>>>(x, xr);
        {
            dim3 grid(NQKV / 32, CDIM / 32);
            round_transpose<<<grid, dim3(32, 8)>>>(w_qkv, wqt, CDIM, NQKV);
        }
        {
            dim3 grid(CDIM / 32, CDIM / 32);
            round_transpose<<<grid, dim3(32, 8)>>>(w_proj, wpt, CDIM, CDIM);
        }
    }
    {
        dim3 grid(NQKV / QBN, MTOT / QBM);   // 6 x 784
        qkv_gemm<<<grid, 256>>>(b_qkv);
    }
    {
        attn_kernel<<<MTOT / 4, 256>>>();
    }
    {
        dim3 grid(CDIM / BN, MTOT / BM);     // 4 x 784
        proj_gemm<<<grid, 256>>>(b_proj, out);
    }
}

// round 15
// speedup vs baseline: 1.2283x; 1.0717x over previous
#include <cuda_runtime.h>
#include <cstdint>

// ---------------- problem constants ----------------
#define BATCH   32
#define HW      56
#define CDIM    512
#define WSZ     7
#define NWIN    2048
#define TTOK    49
#define MTOT    (NWIN * TTOK)   // 100352
#define NQKV    1536

// GEMM tiling (round-12 proven config + 1 extra stage)
#define BM 128
#define BN 128
#define BK 16
#define STAGES 5
#define SPAD 20

// attention smem row pad
#define AP 68

// ---------------- scratch (device globals; no allocs allowed) -------------
__device__ float g_qkv[3ULL * MTOT * CDIM];
__device__ float g_att[(size_t)MTOT * CDIM];            // pre-rounded tf32
__device__ float g_wqt[(size_t)NQKV * CDIM];            // rounded w_qkv^T [n][k]
__device__ float g_wpt[(size_t)CDIM * CDIM];            // rounded w_proj^T [n][k]

// map windowed row m -> source/dest row in [B*3136)
__device__ __forceinline__ int win_row_map(int m) {
    int w = m / TTOK, t = m - w * TTOK;
    int b = w >> 6;
    int wi = (w >> 3) & 7;
    int wj = w & 7;
    int r = t / WSZ, c = t - r * WSZ;
    return (b * HW + wi * WSZ + r) * HW + wj * WSZ + c;
}

__device__ __forceinline__ uint32_t f2tf32(float f) {
    uint32_t u;
    asm("cvt.rna.tf32.f32 %0, %1;" : "=r"(u) : "f"(f));
    return u;
}

__device__ __forceinline__ void cp_async16(void* smem_dst, const void* gmem_src) {
    uint32_t s = (uint32_t)__cvta_generic_to_shared(smem_dst);
    asm volatile("cp.async.cg.shared.global [%0], [%1], 16;" :: "r"(s), "l"(gmem_src));
}
__device__ __forceinline__ void cp_commit() {
    asm volatile("cp.async.commit_group;");
}
template<int N>
__device__ __forceinline__ void cp_wait() {
    asm volatile("cp.async.wait_group %0;" :: "n"(N));
}

__device__ __forceinline__ void ldsm4(uint32_t& r0, uint32_t& r1, uint32_t& r2,
                                      uint32_t& r3, uint32_t addr) {
    asm volatile("ldmatrix.sync.aligned.m8n8.x4.shared.b16 {%0,%1,%2,%3}, [%4];"
                 : "=r"(r0), "=r"(r1), "=r"(r2), "=r"(r3) : "r"(addr));
}

#define MMA_TF32(acc4, a0, a1, a2, a3, b0, b1) \
    asm volatile( \
        "mma.sync.aligned.m16n8k8.row.col.f32.tf32.tf32.f32 " \
        "{%0,%1,%2,%3},{%4,%5,%6,%7},{%8,%9},{%0,%1,%2,%3};" \
        : "+f"((acc4)[0]), "+f"((acc4)[1]), "+f"((acc4)[2]), "+f"((acc4)[3]) \
        : "r"(a0), "r"(a1), "r"(a2), "r"(a3), "r"(b0), "r"(b1))

// ---------------- prep: src[R][C] -> dst[C][R], rounded to tf32 -----------
__global__ void round_transpose(const float* __restrict__ src, float* __restrict__ dst,
                                int R, int C) {
    __shared__ float t[32][33];
    const int bx = blockIdx.x * 32;
    const int by = blockIdx.y * 32;
    const int tx = threadIdx.x;
    for (int i = threadIdx.y; i < 32; i += 8)
        t[i][tx] = src[(size_t)(by + i) * C + bx + tx];
    __syncthreads();
    for (int i = threadIdx.y; i < 32; i += 8)
        dst[(size_t)(bx + i) * R + by + tx] = __uint_as_float(f2tf32(t[tx][i]));
}

// ---------------- tf32 mma GEMM (round-12 config; 5 stages) ----------------
// MODE 0: A = x (raw fp32, gathered via win_row_map; A-frags cvt'd in-loop),
//         W = g_wqt, out -> g_qkv
// MODE 1: A = g_att (pre-rounded, linear), W = g_wpt, out scattered via
//         win_row_map
template<int NDIM, int MODE>
__global__ __launch_bounds__(256, 2) void mma_gemm(
    const float* __restrict__ A,
    const float* __restrict__ bias,
    float* __restrict__ out)
{
    __shared__ __align__(16) float As[STAGES][BM][SPAD];
    __shared__ __align__(16) float Bs[STAGES][BM][SPAD];

    const int tid = threadIdx.x;
    const int lane = tid & 31;
    const int wid  = tid >> 5;
    const int warp_m = wid >> 2;
    const int warp_n = wid & 3;
    const int bn = blockIdx.x * BN;
    const int bm = blockIdx.y * BM;

    const float* Abase = (MODE == 1) ? (const float*)g_att : A;
    const float* Wt    = (MODE == 1) ? (const float*)g_wpt : (const float*)g_wqt;

    const int srow = tid >> 1;
    const int scq  = (tid & 1) * 8;
    const int agrow = (MODE == 0) ? win_row_map(bm + srow) : (bm + srow);
    const float* aptr = Abase + (size_t)agrow * CDIM + scq;
    const float* bptr = Wt + (size_t)(bn + srow) * CDIM + scq;

    float acc[4][4][4] = {};

    const int NIT = CDIM / BK;   // 32

    const int a_row_l = warp_m * 64 + ((lane >> 3) & 1) * 8 + (lane & 7);
    const int a_k_l   = (lane >> 4) * 4;
    const int b_row_l = warp_n * 32 + ((lane >> 4) & 1) * 8 + (lane & 7);
    const int b_k_l   = ((lane >> 3) & 1) * 4;

    const uint32_t sA0 = (uint32_t)__cvta_generic_to_shared(&As[0][0][0]);
    const uint32_t sB0 = (uint32_t)__cvta_generic_to_shared(&Bs[0][0][0]);
    const uint32_t stageB = BM * SPAD * 4;

#pragma unroll
    for (int p = 0; p < STAGES - 1; p++) {
        const float* ap = aptr + p * BK;
        cp_async16(&As[p][srow][scq],     ap);
        cp_async16(&As[p][srow][scq + 4], ap + 4);
        const float* bp = bptr + p * BK;
        cp_async16(&Bs[p][srow][scq],     bp);
        cp_async16(&Bs[p][srow][scq + 4], bp + 4);
        cp_commit();
    }
    cp_wait<STAGES - 2>();
    __syncthreads();

    int s = 0;

#pragma unroll 1
    for (int it = 0; it < NIT; ++it) {
#pragma unroll
        for (int ks = 0; ks < 2; ks++) {
            const int k = ks * 8;
            uint32_t af[4][4];
#pragma unroll
            for (int mt = 0; mt < 4; mt++) {
                const uint32_t addr = sA0 + s * stageB +
                    ((uint32_t)(a_row_l + mt * 16) * SPAD + k + a_k_l) * 4;
                ldsm4(af[mt][0], af[mt][1], af[mt][2], af[mt][3], addr);
            }
            if (MODE == 0) {
#pragma unroll
                for (int mt = 0; mt < 4; mt++)
#pragma unroll
                    for (int j = 0; j < 4; j++)
                        af[mt][j] = f2tf32(__uint_as_float(af[mt][j]));
            }
            uint32_t bf[4][2];
#pragma unroll
            for (int np = 0; np < 2; np++) {
                const uint32_t addr = sB0 + s * stageB +
                    ((uint32_t)(b_row_l + np * 16) * SPAD + k + b_k_l) * 4;
                ldsm4(bf[np * 2][0], bf[np * 2][1], bf[np * 2 + 1][0], bf[np * 2 + 1][1], addr);
            }
#pragma unroll
            for (int mt = 0; mt < 4; mt++)
#pragma unroll
                for (int nt = 0; nt < 4; nt++)
                    MMA_TF32(acc[mt][nt], af[mt][0], af[mt][1], af[mt][2], af[mt][3],
                             bf[nt][0], bf[nt][1]);
        }

        if (it + STAGES - 1 < NIT) {
            const int ls = (s + STAGES - 1 >= STAGES) ? (s - 1) : (s + STAGES - 1);
            const float* ap = aptr + (it + STAGES - 1) * BK;
            cp_async16(&As[ls][srow][scq],     ap);
            cp_async16(&As[ls][srow][scq + 4], ap + 4);
            const float* bp = bptr + (it + STAGES - 1) * BK;
            cp_async16(&Bs[ls][srow][scq],     bp);
            cp_async16(&Bs[ls][srow][scq + 4], bp + 4);
        }
        cp_commit();
        cp_wait<STAGES - 2>();
        __syncthreads();

        s = (s + 1 >= STAGES) ? 0 : (s + 1);
    }

    // ---------------- epilogue ----------------
#pragma unroll
    for (int mt = 0; mt < 4; mt++) {
        const int row0 = bm + warp_m * 64 + mt * 16 + (lane >> 2);
#pragma unroll
        for (int half = 0; half < 2; half++) {
            const int m = row0 + half * 8;
            int dst = 0;
            if (MODE == 1) dst = win_row_map(m);
#pragma unroll
            for (int nt = 0; nt < 4; nt++) {
                const int col0 = bn + warp_n * 32 + nt * 8 + 2 * (lane & 3);
#pragma unroll
                for (int j = 0; j < 2; j++) {
                    const int n = col0 + j;
                    const float v = acc[mt][nt][half * 2 + j] + bias[n];
                    if (MODE == 0) {
                        const int p  = n >> 9;
                        const int cc = n & 511;
                        g_qkv[(size_t)p * MTOT * CDIM + (size_t)m * CDIM + cc] = v;
                    } else {
                        out[(size_t)dst * CDIM + n] = v;
                    }
                }
            }
        }
    }
}

// ---------------- attention (round-12 conflict-free float4) ----------------
__global__ void attn_kernel() {
    __shared__ __align__(16) float qs[4][8 * AP];
    __shared__ __align__(16) float ks[4][8 * AP];
    __shared__ __align__(16) float vs[4][8 * AP];
    __shared__ float ps[4][64];

    const int tid = threadIdx.x;
    const int u   = tid >> 6;
    const int lt  = tid & 63;
    const int unit = blockIdx.x * 4 + u;

    const size_t rowoff = (size_t)unit * CDIM;
    const float* qrow = g_qkv + rowoff;
    const float* krow = g_qkv + (size_t)MTOT * CDIM + rowoff;
    const float* vrow = g_qkv + 2ULL * MTOT * CDIM + rowoff;

#pragma unroll
    for (int j = 0; j < 2; j++) {
        const int f  = lt + 64 * j;
        const int c  = f >> 4;
        const int dd = (f & 15) * 4;
        const int so = c * AP + dd;
        *(float4*)&qs[u][so] = *(const float4*)(qrow + f * 4);
        *(float4*)&ks[u][so] = *(const float4*)(krow + f * 4);
        *(float4*)&vs[u][so] = *(const float4*)(vrow + f * 4);
    }
    __syncthreads();

    const int h = lt >> 3, g = lt & 7;

    float s = 0.f;
    {
        const float* qb = &qs[u][h * AP];
        const float* kb = &ks[u][g * AP];
#pragma unroll
        for (int kk = 0; kk < 16; kk++) {
            float4 qa = *(const float4*)(qb + kk * 4);
            float4 ka = *(const float4*)(kb + kk * 4);
            s = fmaf(qa.x, ka.x, s);
            s = fmaf(qa.y, ka.y, s);
            s = fmaf(qa.z, ka.z, s);
            s = fmaf(qa.w, ka.w, s);
        }
    }
    s *= 0.125f;

    float mx = s;
#pragma unroll
    for (int off = 4; off >= 1; off >>= 1)
        mx = fmaxf(mx, __shfl_xor_sync(0xffffffffu, mx, off));
    float e = __expf(s - mx);
    float sum = e;
#pragma unroll
    for (int off = 4; off >= 1; off >>= 1)
        sum += __shfl_xor_sync(0xffffffffu, sum, off);
    ps[u][lt] = e / sum;
    __syncthreads();

    const int dc = (g + h) & 7;
    const int d0 = dc * 8;
    float p[8];
#pragma unroll
    for (int gg = 0; gg < 8; gg++) p[gg] = ps[u][h * 8 + gg];

    float4 o0 = {0.f, 0.f, 0.f, 0.f};
    float4 o1 = {0.f, 0.f, 0.f, 0.f};
#pragma unroll
    for (int gg = 0; gg < 8; gg++) {
        const float* vb = &vs[u][gg * AP + d0];
        float4 v0 = *(const float4*)(vb);
        float4 v1 = *(const float4*)(vb + 4);
        o0.x = fmaf(p[gg], v0.x, o0.x);
        o0.y = fmaf(p[gg], v0.y, o0.y);
        o0.z = fmaf(p[gg], v0.z, o0.z);
        o0.w = fmaf(p[gg], v0.w, o0.w);
        o1.x = fmaf(p[gg], v1.x, o1.x);
        o1.y = fmaf(p[gg], v1.y, o1.y);
        o1.z = fmaf(p[gg], v1.z, o1.z);
        o1.w = fmaf(p[gg], v1.w, o1.w);
    }

    const int w = unit / TTOK, t = unit - w * TTOK;
    float* obase = g_att + (size_t)w * (TTOK * CDIM) + (size_t)h * (TTOK * 64) + (size_t)t * 64;
    uint4 r0, r1;
    r0.x = f2tf32(o0.x); r0.y = f2tf32(o0.y); r0.z = f2tf32(o0.z); r0.w = f2tf32(o0.w);
    r1.x = f2tf32(o1.x); r1.y = f2tf32(o1.y); r1.z = f2tf32(o1.z); r1.w = f2tf32(o1.w);
    *(uint4*)(obase + d0)     = r0;
    *(uint4*)(obase + d0 + 4) = r1;
}

// ---------------- launch ----------------
extern "C" void kernel_launch(void* const* d_in, const int* in_sizes, int n_in,
                              void* d_out, int out_size) {
    const float* x      = (const float*)d_in[0];
    const float* w_qkv  = (const float*)d_in[1];
    const float* b_qkv  = (const float*)d_in[2];
    const float* w_proj = (const float*)d_in[3];
    const float* b_proj = (const float*)d_in[4];
    float* out = (float*)d_out;

    // prep: rounded+transposed weights only (x is cvt'd on A-fragments)
    {
        float* wqt; cudaGetSymbolAddress((void**)&wqt, g_wqt);
        float* wpt; cudaGetSymbolAddress((void**)&wpt, g_wpt);
        {
            dim3 grid(NQKV / 32, CDIM / 32);
            round_transpose<<<grid, dim3(32, 8)>>>(w_qkv, wqt, CDIM, NQKV);
        }
        {
            dim3 grid(CDIM / 32, CDIM / 32);
            round_transpose<<<grid, dim3(32, 8)>>>(w_proj, wpt, CDIM, CDIM);
        }
    }
    {
        dim3 grid(NQKV / BN, MTOT / BM);   // 12 x 784
        mma_gemm<NQKV, 0><<<grid, 256>>>(x, b_qkv, nullptr);
    }
    {
        attn_kernel<<<MTOT / 4, 256>>>();
    }
    {
        dim3 grid(CDIM / BN, MTOT / BM);   // 4 x 784
        mma_gemm<CDIM, 1><<<grid, 256>>>(nullptr, b_proj, out);
    }
}

// round 16
// speedup vs baseline: 1.2378x; 1.0078x over previous
#include <cuda_runtime.h>
#include <cstdint>

// ---------------- problem constants ----------------
#define BATCH   32
#define HW      56
#define CDIM    512
#define WSZ     7
#define NWIN    2048
#define TTOK    49
#define MTOT    (NWIN * TTOK)   // 100352
#define NQKV    1536

// GEMM tiling (proven config)
#define BM 128
#define BN 128
#define BK 16
#define STAGES 5
#define SPAD 20

// attention smem row pad
#define AP 68

// ---------------- scratch (device globals; no allocs allowed) -------------
__device__ float g_qkv[3ULL * MTOT * CDIM];
__device__ float g_att[(size_t)MTOT * CDIM];            // pre-rounded tf32
__device__ float g_wqt[(size_t)NQKV * CDIM];            // rounded w_qkv^T [n][k]
__device__ float g_wpt[(size_t)CDIM * CDIM];            // rounded w_proj^T [n][k]

// map windowed row m -> source/dest row in [B*3136)
__device__ __forceinline__ int win_row_map(int m) {
    int w = m / TTOK, t = m - w * TTOK;
    int b = w >> 6;
    int wi = (w >> 3) & 7;
    int wj = w & 7;
    int r = t / WSZ, c = t - r * WSZ;
    return (b * HW + wi * WSZ + r) * HW + wj * WSZ + c;
}

__device__ __forceinline__ uint32_t f2tf32(float f) {
    uint32_t u;
    asm("cvt.rna.tf32.f32 %0, %1;" : "=r"(u) : "f"(f));
    return u;
}

__device__ __forceinline__ void cp_async16(void* smem_dst, const void* gmem_src) {
    uint32_t s = (uint32_t)__cvta_generic_to_shared(smem_dst);
    asm volatile("cp.async.cg.shared.global [%0], [%1], 16;" :: "r"(s), "l"(gmem_src));
}
__device__ __forceinline__ void cp_commit() {
    asm volatile("cp.async.commit_group;");
}
template<int N>
__device__ __forceinline__ void cp_wait() {
    asm volatile("cp.async.wait_group %0;" :: "n"(N));
}

__device__ __forceinline__ void ldsm4(uint32_t& r0, uint32_t& r1, uint32_t& r2,
                                      uint32_t& r3, uint32_t addr) {
    asm volatile("ldmatrix.sync.aligned.m8n8.x4.shared.b16 {%0,%1,%2,%3}, [%4];"
                 : "=r"(r0), "=r"(r1), "=r"(r2), "=r"(r3) : "r"(addr));
}

#define MMA_TF32(acc4, a0, a1, a2, a3, b0, b1) \
    asm volatile( \
        "mma.sync.aligned.m16n8k8.row.col.f32.tf32.tf32.f32 " \
        "{%0,%1,%2,%3},{%4,%5,%6,%7},{%8,%9},{%0,%1,%2,%3};" \
        : "+f"((acc4)[0]), "+f"((acc4)[1]), "+f"((acc4)[2]), "+f"((acc4)[3]) \
        : "r"(a0), "r"(a1), "r"(a2), "r"(a3), "r"(b0), "r"(b1))

// ---------------- prep: src[R][C] -> dst[C][R], rounded to tf32 -----------
__global__ void round_transpose(const float* __restrict__ src, float* __restrict__ dst,
                                int R, int C) {
    __shared__ float t[32][33];
    const int bx = blockIdx.x * 32;
    const int by = blockIdx.y * 32;
    const int tx = threadIdx.x;
    for (int i = threadIdx.y; i < 32; i += 8)
        t[i][tx] = src[(size_t)(by + i) * C + bx + tx];
    __syncthreads();
    for (int i = threadIdx.y; i < 32; i += 8)
        dst[(size_t)(bx + i) * R + by + tx] = __uint_as_float(f2tf32(t[tx][i]));
}

// ---------------- tf32 mma GEMM (proven config; 5 stages) ------------------
// MODE 0: A = x (raw fp32, gathered via win_row_map; A-frags cvt'd in-loop),
//         W = g_wqt, out -> g_qkv
// MODE 1: A = g_att (pre-rounded, linear), W = g_wpt, out scattered via
//         win_row_map
template<int NDIM, int MODE>
__global__ __launch_bounds__(256, 2) void mma_gemm(
    const float* __restrict__ A,
    const float* __restrict__ bias,
    float* __restrict__ out)
{
    __shared__ __align__(16) float As[STAGES][BM][SPAD];
    __shared__ __align__(16) float Bs[STAGES][BM][SPAD];

    const int tid = threadIdx.x;
    const int lane = tid & 31;
    const int wid  = tid >> 5;
    const int warp_m = wid >> 2;
    const int warp_n = wid & 3;
    const int bn = blockIdx.x * BN;
    const int bm = blockIdx.y * BM;

    const float* Abase = (MODE == 1) ? (const float*)g_att : A;
    const float* Wt    = (MODE == 1) ? (const float*)g_wpt : (const float*)g_wqt;

    const int srow = tid >> 1;
    const int scq  = (tid & 1) * 8;
    const int agrow = (MODE == 0) ? win_row_map(bm + srow) : (bm + srow);
    const float* aptr = Abase + (size_t)agrow * CDIM + scq;
    const float* bptr = Wt + (size_t)(bn + srow) * CDIM + scq;

    float acc[4][4][4] = {};

    const int NIT = CDIM / BK;   // 32

    const int a_row_l = warp_m * 64 + ((lane >> 3) & 1) * 8 + (lane & 7);
    const int a_k_l   = (lane >> 4) * 4;
    const int b_row_l = warp_n * 32 + ((lane >> 4) & 1) * 8 + (lane & 7);
    const int b_k_l   = ((lane >> 3) & 1) * 4;

    const uint32_t sA0 = (uint32_t)__cvta_generic_to_shared(&As[0][0][0]);
    const uint32_t sB0 = (uint32_t)__cvta_generic_to_shared(&Bs[0][0][0]);
    const uint32_t stageB = BM * SPAD * 4;

#pragma unroll
    for (int p = 0; p < STAGES - 1; p++) {
        const float* ap = aptr + p * BK;
        cp_async16(&As[p][srow][scq],     ap);
        cp_async16(&As[p][srow][scq + 4], ap + 4);
        const float* bp = bptr + p * BK;
        cp_async16(&Bs[p][srow][scq],     bp);
        cp_async16(&Bs[p][srow][scq + 4], bp + 4);
        cp_commit();
    }
    cp_wait<STAGES - 2>();
    __syncthreads();

    int s = 0;

#pragma unroll 1
    for (int it = 0; it < NIT; ++it) {
#pragma unroll
        for (int ks = 0; ks < 2; ks++) {
            const int k = ks * 8;
            uint32_t af[4][4];
#pragma unroll
            for (int mt = 0; mt < 4; mt++) {
                const uint32_t addr = sA0 + s * stageB +
                    ((uint32_t)(a_row_l + mt * 16) * SPAD + k + a_k_l) * 4;
                ldsm4(af[mt][0], af[mt][1], af[mt][2], af[mt][3], addr);
            }
            if (MODE == 0) {
#pragma unroll
                for (int mt = 0; mt < 4; mt++)
#pragma unroll
                    for (int j = 0; j < 4; j++)
                        af[mt][j] = f2tf32(__uint_as_float(af[mt][j]));
            }
            uint32_t bf[4][2];
#pragma unroll
            for (int np = 0; np < 2; np++) {
                const uint32_t addr = sB0 + s * stageB +
                    ((uint32_t)(b_row_l + np * 16) * SPAD + k + b_k_l) * 4;
                ldsm4(bf[np * 2][0], bf[np * 2][1], bf[np * 2 + 1][0], bf[np * 2 + 1][1], addr);
            }
#pragma unroll
            for (int mt = 0; mt < 4; mt++)
#pragma unroll
                for (int nt = 0; nt < 4; nt++)
                    MMA_TF32(acc[mt][nt], af[mt][0], af[mt][1], af[mt][2], af[mt][3],
                             bf[nt][0], bf[nt][1]);
        }

        if (it + STAGES - 1 < NIT) {
            const int ls = (s + STAGES - 1 >= STAGES) ? (s - 1) : (s + STAGES - 1);
            const float* ap = aptr + (it + STAGES - 1) * BK;
            cp_async16(&As[ls][srow][scq],     ap);
            cp_async16(&As[ls][srow][scq + 4], ap + 4);
            const float* bp = bptr + (it + STAGES - 1) * BK;
            cp_async16(&Bs[ls][srow][scq],     bp);
            cp_async16(&Bs[ls][srow][scq + 4], bp + 4);
        }
        cp_commit();
        cp_wait<STAGES - 2>();
        __syncthreads();

        s = (s + 1 >= STAGES) ? 0 : (s + 1);
    }

    // ---------------- epilogue ----------------
#pragma unroll
    for (int mt = 0; mt < 4; mt++) {
        const int row0 = bm + warp_m * 64 + mt * 16 + (lane >> 2);
#pragma unroll
        for (int half = 0; half < 2; half++) {
            const int m = row0 + half * 8;
            int dst = 0;
            if (MODE == 1) dst = win_row_map(m);
#pragma unroll
            for (int nt = 0; nt < 4; nt++) {
                const int col0 = bn + warp_n * 32 + nt * 8 + 2 * (lane & 3);
#pragma unroll
                for (int j = 0; j < 2; j++) {
                    const int n = col0 + j;
                    const float v = acc[mt][nt][half * 2 + j] + bias[n];
                    if (MODE == 0) {
                        const int p  = n >> 9;
                        const int cc = n & 511;
                        g_qkv[(size_t)p * MTOT * CDIM + (size_t)m * CDIM + cc] = v;
                    } else {
                        out[(size_t)dst * CDIM + n] = v;
                    }
                }
            }
        }
    }
}

// ---------------- attention: single-sync, shuffle softmax ------------------
// per unit: S[h][g] = q[h,:]·k[g,:]/8; softmax over g; O = P V.
// p-values gathered via intra-8-lane shuffles (no smem, no 2nd barrier).
__global__ void attn_kernel() {
    __shared__ __align__(16) float qs[4][8 * AP];
    __shared__ __align__(16) float ks[4][8 * AP];
    __shared__ __align__(16) float vs[4][8 * AP];

    const int tid = threadIdx.x;
    const int u   = tid >> 6;
    const int lt  = tid & 63;
    const int lane = tid & 31;
    const int unit = blockIdx.x * 4 + u;

    const size_t rowoff = (size_t)unit * CDIM;
    const float* qrow = g_qkv + rowoff;
    const float* krow = g_qkv + (size_t)MTOT * CDIM + rowoff;
    const float* vrow = g_qkv + 2ULL * MTOT * CDIM + rowoff;

#pragma unroll
    for (int j = 0; j < 2; j++) {
        const int f  = lt + 64 * j;
        const int c  = f >> 4;
        const int dd = (f & 15) * 4;
        const int so = c * AP + dd;
        *(float4*)&qs[u][so] = *(const float4*)(qrow + f * 4);
        *(float4*)&ks[u][so] = *(const float4*)(krow + f * 4);
        *(float4*)&vs[u][so] = *(const float4*)(vrow + f * 4);
    }
    __syncthreads();

    const int h = lt >> 3, g = lt & 7;

    float s = 0.f;
    {
        const float* qb = &qs[u][h * AP];
        const float* kb = &ks[u][g * AP];
#pragma unroll
        for (int kk = 0; kk < 16; kk++) {
            float4 qa = *(const float4*)(qb + kk * 4);
            float4 ka = *(const float4*)(kb + kk * 4);
            s = fmaf(qa.x, ka.x, s);
            s = fmaf(qa.y, ka.y, s);
            s = fmaf(qa.z, ka.z, s);
            s = fmaf(qa.w, ka.w, s);
        }
    }
    s *= 0.125f;

    // softmax over g (8-lane groups within warp)
    float mx = s;
#pragma unroll
    for (int off = 4; off >= 1; off >>= 1)
        mx = fmaxf(mx, __shfl_xor_sync(0xffffffffu, mx, off));
    float e = __expf(s - mx);
    float sum = e;
#pragma unroll
    for (int off = 4; off >= 1; off >>= 1)
        sum += __shfl_xor_sync(0xffffffffu, sum, off);
    const float pv = e / sum;

    // gather this h-row's 8 probabilities via shuffle (no smem, no barrier)
    const int gbase = lane & ~7;     // start of this thread's 8-lane group
    float p[8];
#pragma unroll
    for (int gg = 0; gg < 8; gg++)
        p[gg] = __shfl_sync(0xffffffffu, pv, gbase + gg);

    // O[h][d] for d-chunk dc=(g+h)&7: rotation -> multicast-friendly v reads
    const int dc = (g + h) & 7;
    const int d0 = dc * 8;

    float4 o0 = {0.f, 0.f, 0.f, 0.f};
    float4 o1 = {0.f, 0.f, 0.f, 0.f};
#pragma unroll
    for (int gg = 0; gg < 8; gg++) {
        const float* vb = &vs[u][gg * AP + d0];
        float4 v0 = *(const float4*)(vb);
        float4 v1 = *(const float4*)(vb + 4);
        o0.x = fmaf(p[gg], v0.x, o0.x);
        o0.y = fmaf(p[gg], v0.y, o0.y);
        o0.z = fmaf(p[gg], v0.z, o0.z);
        o0.w = fmaf(p[gg], v0.w, o0.w);
        o1.x = fmaf(p[gg], v1.x, o1.x);
        o1.y = fmaf(p[gg], v1.y, o1.y);
        o1.z = fmaf(p[gg], v1.z, o1.z);
        o1.w = fmaf(p[gg], v1.w, o1.w);
    }

    const int w = unit / TTOK, t = unit - w * TTOK;
    float* obase = g_att + (size_t)w * (TTOK * CDIM) + (size_t)h * (TTOK * 64) + (size_t)t * 64;
    uint4 r0, r1;
    r0.x = f2tf32(o0.x); r0.y = f2tf32(o0.y); r0.z = f2tf32(o0.z); r0.w = f2tf32(o0.w);
    r1.x = f2tf32(o1.x); r1.y = f2tf32(o1.y); r1.z = f2tf32(o1.z); r1.w = f2tf32(o1.w);
    *(uint4*)(obase + d0)     = r0;
    *(uint4*)(obase + d0 + 4) = r1;
}

// ---------------- launch ----------------
extern "C" void kernel_launch(void* const* d_in, const int* in_sizes, int n_in,
                              void* d_out, int out_size) {
    const float* x      = (const float*)d_in[0];
    const float* w_qkv  = (const float*)d_in[1];
    const float* b_qkv  = (const float*)d_in[2];
    const float* w_proj = (const float*)d_in[3];
    const float* b_proj = (const float*)d_in[4];
    float* out = (float*)d_out;

    // prep: rounded+transposed weights only (x is cvt'd on A-fragments)
    {
        float* wqt; cudaGetSymbolAddress((void**)&wqt, g_wqt);
        float* wpt; cudaGetSymbolAddress((void**)&wpt, g_wpt);
        {
            dim3 grid(NQKV / 32, CDIM / 32);
            round_transpose<<<grid, dim3(32, 8)>>>(w_qkv, wqt, CDIM, NQKV);
        }
        {
            dim3 grid(CDIM / 32, CDIM / 32);
            round_transpose<<<grid, dim3(32, 8)>>>(w_proj, wpt, CDIM, CDIM);
        }
    }
    {
        dim3 grid(NQKV / BN, MTOT / BM);   // 12 x 784
        mma_gemm<NQKV, 0><<<grid, 256>>>(x, b_qkv, nullptr);
    }
    {
        attn_kernel<<<MTOT / 4, 256>>>();
    }
    {
        dim3 grid(CDIM / BN, MTOT / BM);   // 4 x 784
        mma_gemm<CDIM, 1><<<grid, 256>>>(nullptr, b_proj, out);
    }
}